// round 4
// baseline (speedup 1.0000x reference)
#include <cuda_runtime.h>
#include <math_constants.h>

// Shapes (fixed): x: [B=32, C=256, H=128, W=128] float32
#define B_   32
#define C_   256
#define HW_  16384   // 128*128
#define HW4_ 4096    // HW / 4 (float4 groups)

#define GROUPS 4
#define CPG    32            // CTAs per group
#define BPG    8             // batches per group (4*8 = 32)
#define NCTA   (GROUPS*CPG)  // 128 CTAs, all co-resident on 148 SMs
#define THREADS 512
#define SLICE4 (HW4_/CPG)    // 128 float4 per channel per CTA slice

#define ENTRO_BLOCKS 64

// Scratch (device globals — no allocation allowed)
__device__ float g_pp[B_ * C_ * CPG];      // partial pooled [b][c][slice], 1 MB
__device__ float g_xn[B_ * HW_];           // 2 MB
__device__ float g_ssum[NCTA];             // sigmoid partial per CTA
__device__ float g_entro[HW_];             // 64 KB
__device__ float g_mm[ENTRO_BLOCKS * 2];   // per-block (min,max) partials
__device__ int   g_hist[256];
__device__ int   g_bar[GROUPS * BPG * 2];  // group barriers (phase1, phase2)

// ---------------------------------------------------------------------------
// K0: zero barrier counters + global histogram (re-run on every graph replay)
// ---------------------------------------------------------------------------
__global__ void k_init() {
    g_hist[threadIdx.x] = 0;
    if (threadIdx.x < GROUPS * BPG * 2) g_bar[threadIdx.x] = 0;
}

// ---------------------------------------------------------------------------
// K1 (fused pool + xn): persistent groups. Each group of 32 CTAs processes
// its 8 batches serially: phase1 pools the batch (DRAM read), group barrier,
// phase2 re-reads the SAME 16MB (now L2-hot) to compute xn + sigmoid partials.
// All reductions fixed-order -> deterministic.
// ---------------------------------------------------------------------------
__global__ void __launch_bounds__(THREADS) k_fused(const float* __restrict__ x) {
    const int cta  = blockIdx.x;
    const int g    = cta / CPG;
    const int s    = cta % CPG;        // slice id within group
    const int tid  = threadIdx.x;
    const int w    = tid >> 5;
    const int lane = tid & 31;

    __shared__ float  pw[C_];
    __shared__ float4 sm4[4][128];
    __shared__ float  sred[THREADS];

    const float4* __restrict__ x4 = reinterpret_cast<const float4*>(x);
    const int sbase = s * SLICE4;
    float sig_acc = 0.0f;

    for (int it = 0; it < BPG; it++) {
        const int b = g * BPG + it;
        const float4* __restrict__ xb = x4 + (size_t)b * C_ * HW4_;

        // ---- phase 1: per-channel partial sums over this CTA's spatial slice
        // warp w handles channels [w*16, w*16+16)
        for (int ci = 0; ci < 16; ci++) {
            const int c = w * 16 + ci;
            const float4* __restrict__ p = xb + (size_t)c * HW4_ + sbase;
            float4 v0 = p[lane];
            float4 v1 = p[lane + 32];
            float4 v2 = p[lane + 64];
            float4 v3 = p[lane + 96];
            float t = ((v0.x + v0.y) + (v0.z + v0.w))
                    + ((v1.x + v1.y) + (v1.z + v1.w))
                    + ((v2.x + v2.y) + (v2.z + v2.w))
                    + ((v3.x + v3.y) + (v3.z + v3.w));
#pragma unroll
            for (int o = 16; o > 0; o >>= 1)
                t += __shfl_down_sync(0xffffffffu, t, o);
            if (lane == 0) g_pp[(b * C_ + c) * CPG + s] = t;
        }

        // ---- group barrier: all 32 slices' partials visible
        __syncthreads();
        __threadfence();
        if (tid == 0) {
            atomicAdd(&g_bar[(g * BPG + it) * 2], 1);
            while (atomicAdd(&g_bar[(g * BPG + it) * 2], 0) < CPG) __nanosleep(128);
        }
        __syncthreads();
        __threadfence();

        // ---- combine partials -> pooled weights in smem (fixed order)
        if (tid < C_) {
            const float4* pp4 =
                reinterpret_cast<const float4*>(&g_pp[(b * C_ + tid) * CPG]);
            float acc = 0.0f;
#pragma unroll
            for (int k = 0; k < CPG / 4; k++) {
                float4 v = __ldcg(&pp4[k]);
                acc += ((v.x + v.y) + (v.z + v.w));
            }
            pw[tid] = acc * (1.0f / (float)HW_);
        }
        __syncthreads();

        // ---- phase 2: xn over the same slice (L2-hot). Channel range split
        // into 4 quarters across the 512 threads.
        const int col = tid & 127;
        const int q   = tid >> 7;   // 0..3
        {
            const float4* __restrict__ p =
                xb + (size_t)(q * 64) * HW4_ + sbase + col;
            float ax = 0.f, ay = 0.f, az = 0.f, aw = 0.f;
#pragma unroll 8
            for (int ci = 0; ci < 64; ci++) {
                float4 v = p[(size_t)ci * HW4_];
                float wgt = pw[q * 64 + ci];
                ax = fmaf(v.x, wgt, ax);
                ay = fmaf(v.y, wgt, ay);
                az = fmaf(v.z, wgt, az);
                aw = fmaf(v.w, wgt, aw);
            }
            sm4[q][col] = make_float4(ax, ay, az, aw);
        }
        __syncthreads();
        if (q == 0) {
            float4 a0 = sm4[0][col], a1 = sm4[1][col],
                   a2 = sm4[2][col], a3 = sm4[3][col];
            const float inv = 1.0f / (float)C_;
            float4 xn;
            xn.x = ((a0.x + a1.x) + (a2.x + a3.x)) * inv;
            xn.y = ((a0.y + a1.y) + (a2.y + a3.y)) * inv;
            xn.z = ((a0.z + a1.z) + (a2.z + a3.z)) * inv;
            xn.w = ((a0.w + a1.w) + (a2.w + a3.w)) * inv;
            reinterpret_cast<float4*>(g_xn)[(size_t)b * HW4_ + sbase + col] = xn;

            sig_acc += 1.0f / (1.0f + __expf(-xn.x))
                     + 1.0f / (1.0f + __expf(-xn.y))
                     + 1.0f / (1.0f + __expf(-xn.z))
                     + 1.0f / (1.0f + __expf(-xn.w));
        }

        // ---- group barrier: lockstep before next batch (bounds L2 footprint)
        __syncthreads();
        if (tid == 0) {
            atomicAdd(&g_bar[(g * BPG + it) * 2 + 1], 1);
            while (atomicAdd(&g_bar[(g * BPG + it) * 2 + 1], 0) < CPG) __nanosleep(128);
        }
        __syncthreads();
    }

    // ---- per-CTA sigmoid partial (deterministic tree over 512 slots)
    sred[tid] = sig_acc;
    __syncthreads();
#pragma unroll
    for (int o = 256; o > 0; o >>= 1) {
        if (tid < o) sred[tid] += sred[tid + o];
        __syncthreads();
    }
    if (tid == 0) g_ssum[cta] = sred[0];
}

// ---------------------------------------------------------------------------
// K2: entro[sp] = mean over b of xn[b,sp]; per-block min/max partials.
// ---------------------------------------------------------------------------
__global__ void __launch_bounds__(256) k_entro() {
    const int sp = blockIdx.x * 256 + threadIdx.x;
    float a = 0.0f;
#pragma unroll
    for (int b = 0; b < B_; b++) a += g_xn[(size_t)b * HW_ + sp];
    float v = a * (1.0f / (float)B_);
    g_entro[sp] = v;

    __shared__ float smin[256], smax[256];
    smin[threadIdx.x] = v;
    smax[threadIdx.x] = v;
    __syncthreads();
#pragma unroll
    for (int o = 128; o > 0; o >>= 1) {
        if (threadIdx.x < o) {
            smin[threadIdx.x] = fminf(smin[threadIdx.x], smin[threadIdx.x + o]);
            smax[threadIdx.x] = fmaxf(smax[threadIdx.x], smax[threadIdx.x + o]);
        }
        __syncthreads();
    }
    if (threadIdx.x == 0) {
        g_mm[blockIdx.x * 2 + 0] = smin[0];
        g_mm[blockIdx.x * 2 + 1] = smax[0];
    }
}

// ---------------------------------------------------------------------------
// K3: 64 blocks: reduce min/max partials (redundant), bin 256 elements each
// into shared histogram, flush to global histogram.
// ---------------------------------------------------------------------------
__global__ void __launch_bounds__(256) k_hist() {
    const int tid = threadIdx.x;

    __shared__ float smin[64], smax[64];
    __shared__ int hist[256];
    hist[tid] = 0;
    if (tid < 64) {
        smin[tid] = g_mm[tid * 2 + 0];
        smax[tid] = g_mm[tid * 2 + 1];
    }
    __syncthreads();
#pragma unroll
    for (int o = 32; o > 0; o >>= 1) {
        if (tid < o) {
            smin[tid] = fminf(smin[tid], smin[tid + o]);
            smax[tid] = fmaxf(smax[tid], smax[tid + o]);
        }
        __syncthreads();
    }
    const float emin = smin[0];
    const float denom = smax[0] - emin;

    float e = (g_entro[blockIdx.x * 256 + tid] - emin) / denom * 255.0f;
    int bin = (int)floorf(e * (256.0f / 255.0f));
    bin = min(max(bin, 0), 255);
    atomicAdd(&hist[bin], 1);
    __syncthreads();

    if (hist[tid] != 0) atomicAdd(&g_hist[tid], hist[tid]);
}

// ---------------------------------------------------------------------------
// K4: entropy over 256 bins + nz, sigmoid-sum reduce (128 partials), output.
// ---------------------------------------------------------------------------
__global__ void __launch_bounds__(256) k_out(float* __restrict__ out) {
    const int tid = threadIdx.x;

    __shared__ double sd[256];
    sd[tid] = (tid < NCTA) ? (double)g_ssum[tid] : 0.0;
    __syncthreads();
#pragma unroll
    for (int o = 128; o > 0; o >>= 1) {
        if (tid < o) sd[tid] += sd[tid + o];
        __syncthreads();
    }

    __shared__ float ssum[256];
    __shared__ int   snz[256];
    int h = g_hist[tid];
    float hisv = (float)h * (1.0f / (float)HW_);
    ssum[tid] = hisv * (-logf(hisv + 1e-8f));
    snz[tid]  = (h != 0) ? 1 : 0;
    __syncthreads();
#pragma unroll
    for (int o = 128; o > 0; o >>= 1) {
        if (tid < o) {
            ssum[tid] += ssum[tid + o];
            snz[tid]  += snz[tid + o];
        }
        __syncthreads();
    }

    if (tid == 0) {
        float s = (float)(sd[0] / (double)((size_t)B_ * HW_));
        float entro_final = ssum[0] / (float)snz[0];
        out[0] = s + entro_final * 10.0f;
    }
}

// ---------------------------------------------------------------------------
extern "C" void kernel_launch(void* const* d_in, const int* in_sizes, int n_in,
                              void* d_out, int out_size) {
    const float* x = (const float*)d_in[0];
    float* out = (float*)d_out;

    k_init<<<1, 256>>>();
    k_fused<<<NCTA, THREADS>>>(x);
    k_entro<<<ENTRO_BLOCKS, 256>>>();
    k_hist<<<ENTRO_BLOCKS, 256>>>();
    k_out<<<1, 256>>>(out);
}